// round 5
// baseline (speedup 1.0000x reference)
#include <cuda_runtime.h>
#include <math.h>

// Problem constants
#define VOCAB 50257
#define EMB   16
#define BS    8
#define MCW   512
#define NTOK  (BS * MCW)      // 4096 tokens

// Scratch (device globals: allocation-free)
__device__ float g_Q[NTOK * EMB];
__device__ float g_K[NTOK * EMB];
__device__ float g_V[NTOK * EMB];
__device__ float g_Wt[BS * MCW * MCW];   // g_Wt[b][k][q] : softmaxed weight (b,q,k), k-major
__device__ float g_out[NTOK * EMB];

// ---------------------------------------------------------------------------
// packed fp32x2 helpers (Blackwell)
// ---------------------------------------------------------------------------
__device__ __forceinline__ float2 fma2(float2 a, float2 b, float2 c) {
    float2 d;
    asm("{\n\t"
        ".reg .b64 ra, rb, rc, rd;\n\t"
        "mov.b64 ra, {%2, %3};\n\t"
        "mov.b64 rb, {%4, %5};\n\t"
        "mov.b64 rc, {%6, %7};\n\t"
        "fma.rn.f32x2 rd, ra, rb, rc;\n\t"
        "mov.b64 {%0, %1}, rd;\n\t"
        "}"
        : "=f"(d.x), "=f"(d.y)
        : "f"(a.x), "f"(a.y), "f"(b.x), "f"(b.y), "f"(c.x), "f"(c.y));
    return d;
}

__device__ __forceinline__ float2 add2(float2 a, float2 b) {
    float2 d;
    asm("{\n\t"
        ".reg .b64 ra, rb, rd;\n\t"
        "mov.b64 ra, {%2, %3};\n\t"
        "mov.b64 rb, {%4, %5};\n\t"
        "add.rn.f32x2 rd, ra, rb;\n\t"
        "mov.b64 {%0, %1}, rd;\n\t"
        "}"
        : "=f"(d.x), "=f"(d.y)
        : "f"(a.x), "f"(a.y), "f"(b.x), "f"(b.y));
    return d;
}

__device__ __forceinline__ float2 dup(float x) { return make_float2(x, x); }

// ---------------------------------------------------------------------------
// Kernel 1: embedding gather + Q/K/V projections
// ---------------------------------------------------------------------------
__global__ void qkv_kernel(const int* __restrict__ x,
                           const float* __restrict__ emb_table,
                           const float* __restrict__ Wq, const float* __restrict__ bq,
                           const float* __restrict__ Wk, const float* __restrict__ bk,
                           const float* __restrict__ Wv, const float* __restrict__ bv) {
    __shared__ float semb[16][EMB];
    int lt = threadIdx.x >> 4;     // local token 0..15
    int e  = threadIdx.x & 15;     // output dim
    int tok = blockIdx.x * 16 + lt;
    int id = x[tok];
    semb[lt][e] = emb_table[id * EMB + e];
    __syncthreads();

    float q = bq[e], k = bk[e], v = bv[e];
#pragma unroll
    for (int j = 0; j < EMB; ++j) {
        float ej = semb[lt][j];
        q = fmaf(Wq[e * EMB + j], ej, q);
        k = fmaf(Wk[e * EMB + j], ej, k);
        v = fmaf(Wv[e * EMB + j], ej, v);
    }
    g_Q[tok * EMB + e] = q;
    g_K[tok * EMB + e] = k;
    g_V[tok * EMB + e] = v;
}

// ---------------------------------------------------------------------------
// Block reduction over 512 threads (16 warps)
// ---------------------------------------------------------------------------
__device__ __forceinline__ float block_reduce(float v, bool do_max, float* sred, int tid) {
#pragma unroll
    for (int o = 16; o > 0; o >>= 1) {
        float s = __shfl_xor_sync(0xffffffffu, v, o);
        v = do_max ? fmaxf(v, s) : (v + s);
    }
    if ((tid & 31) == 0) sred[tid >> 5] = v;
    __syncthreads();
    if (tid < 32) {
        float t = (tid < 16) ? sred[tid] : (do_max ? -INFINITY : 0.0f);
#pragma unroll
        for (int o = 8; o > 0; o >>= 1) {
            float s = __shfl_xor_sync(0xffffffffu, t, o);
            t = do_max ? fmaxf(t, s) : (t + s);
        }
        if (tid == 0) sred[0] = t;
    }
    __syncthreads();
    float r = sred[0];
    __syncthreads();   // protect sred reuse
    return r;
}

// ---------------------------------------------------------------------------
// Kernel 2: scores + mask + zero->-inf quirk + softmax over QUERY axis
// grid: (MCW/8, BS); block: 512 threads (q). writes g_Wt[b][k][q]
// ---------------------------------------------------------------------------
__global__ void attn_weights_kernel() {
    int kc0 = blockIdx.x * 8;
    int b   = blockIdx.y;
    int tid = threadIdx.x;   // q index

    __shared__ float sK[8][EMB];
    __shared__ float sred[16];

    const float4* qrow = reinterpret_cast<const float4*>(g_Q + (b * MCW + tid) * EMB);
    float4 q0 = qrow[0], q1 = qrow[1], q2 = qrow[2], q3 = qrow[3];

    if (tid < 8 * EMB) {
        sK[tid >> 4][tid & 15] = g_K[(b * MCW + kc0 + (tid >> 4)) * EMB + (tid & 15)];
    }
    __syncthreads();

#pragma unroll
    for (int kc = 0; kc < 8; ++kc) {
        int kcol = kc0 + kc;
        const float* kv = sK[kc];
        float s = 0.0f;
        s = fmaf(q0.x, kv[0],  s); s = fmaf(q0.y, kv[1],  s);
        s = fmaf(q0.z, kv[2],  s); s = fmaf(q0.w, kv[3],  s);
        s = fmaf(q1.x, kv[4],  s); s = fmaf(q1.y, kv[5],  s);
        s = fmaf(q1.z, kv[6],  s); s = fmaf(q1.w, kv[7],  s);
        s = fmaf(q2.x, kv[8],  s); s = fmaf(q2.y, kv[9],  s);
        s = fmaf(q2.z, kv[10], s); s = fmaf(q2.w, kv[11], s);
        s = fmaf(q3.x, kv[12], s); s = fmaf(q3.y, kv[13], s);
        s = fmaf(q3.z, kv[14], s); s = fmaf(q3.w, kv[15], s);

        // mask: keep only k <= q ; quirk: exact-zero scores -> -inf
        float val = (kcol <= tid && s != 0.0f) ? s : -INFINITY;

        float m = block_reduce(val, true, sred, tid);
        float p = __expf(val - m);
        float sum = block_reduce(p, false, sred, tid);
        float w = p / sum;

        g_Wt[((size_t)(b * MCW + kcol)) * MCW + tid] = w;   // coalesced over q
    }
}

// ---------------------------------------------------------------------------
// Kernel 3: out[b,w,e] = sum_p Wt[b][p][w] * V[b,p,e]
// ---------------------------------------------------------------------------
__global__ void attn_out_kernel() {
    int b  = blockIdx.y;
    int w  = blockIdx.x * 16 + (threadIdx.x & 15);
    int e  = threadIdx.x >> 4;

    __shared__ float sV[MCW * EMB];   // 32 KB
    const float* Vb = g_V + b * MCW * EMB;
    for (int i = threadIdx.x; i < MCW * EMB; i += 256) sV[i] = Vb[i];
    __syncthreads();

    const float* Wtb = g_Wt + (size_t)b * MCW * MCW;
    float acc = 0.0f;
#pragma unroll 8
    for (int p = 0; p < MCW; ++p)
        acc = fmaf(Wtb[p * MCW + w], sV[p * EMB + e], acc);

    g_out[(b * MCW + w) * EMB + e] = acc;
}

// ---------------------------------------------------------------------------
// Kernel 4: logits[t, v] = dot(out[t,:], Wl[v,:]) + bl[v]
// Thread owns 4 vocab rows as 2 f32x2 pairs. Token vectors staged in smem
// UNDUPLICATED (float4); dup pairs for FFMA2 built with register MOVs on the
// idle ALU pipe. 4 LDS.128 per token instead of 8 -> halves L1/smem traffic,
// which ncu showed as the binding resource (L1TEX 75.8%).
// ---------------------------------------------------------------------------
#define TC  256      // tokens per block
#define VB  1024     // vocab per block (256 threads * 4)

__global__ void __launch_bounds__(256, 2)
logits_kernel(const float* __restrict__ Wl, const float* __restrict__ bl,
              float* __restrict__ logits) {
    __shared__ float4 stok[TC * 4];   // 16 KB : stok[t*4+j] = out[t][4j..4j+3]

    int tid   = threadIdx.x;
    int t0    = blockIdx.y * TC;
    int vbase = blockIdx.x * VB;

    // stage plain token vectors (float4)
    const float4* src = reinterpret_cast<const float4*>(g_out + t0 * EMB);
    for (int i = tid; i < TC * 4; i += 256) {
        stok[i] = src[i];
    }

    // this thread's 4 vocab rows: pair0 = {v0, v0+1}, pair1 = {v2, v2+1}
    int v0 = vbase + 2 * tid;
    int v2 = vbase + 512 + 2 * tid;

    float2 wl0[EMB], wl1[EMB];
    bool a0 = (v0 < VOCAB), a1 = (v0 + 1 < VOCAB);
    bool c0 = (v2 < VOCAB), c1 = (v2 + 1 < VOCAB);
#pragma unroll
    for (int k = 0; k < EMB; ++k) {
        wl0[k] = make_float2(a0 ? Wl[v0 * EMB + k] : 0.0f,
                             a1 ? Wl[(v0 + 1) * EMB + k] : 0.0f);
        wl1[k] = make_float2(c0 ? Wl[v2 * EMB + k] : 0.0f,
                             c1 ? Wl[(v2 + 1) * EMB + k] : 0.0f);
    }
    float2 b0 = make_float2(a0 ? bl[v0] : 0.0f, a1 ? bl[v0 + 1] : 0.0f);
    float2 b1 = make_float2(c0 ? bl[v2] : 0.0f, c1 ? bl[v2 + 1] : 0.0f);

    __syncthreads();

    for (int t = 0; t < TC; ++t) {
        const float4* tk = stok + t * 4;
        // 4 independent chains, depth 8
        float2 p00 = b0;
        float2 p01 = make_float2(0.0f, 0.0f);
        float2 p10 = b1;
        float2 p11 = make_float2(0.0f, 0.0f);

        // first half of the token vector (k = 0..7)
        {
            float4 A = tk[0];
            float4 B = tk[1];
            float2 d0 = dup(A.x), d1 = dup(A.y), d2 = dup(A.z), d3 = dup(A.w);
            float2 d4 = dup(B.x), d5 = dup(B.y), d6 = dup(B.z), d7 = dup(B.w);
            p00 = fma2(wl0[0], d0, p00);  p10 = fma2(wl1[0], d0, p10);
            p01 = fma2(wl0[1], d1, p01);  p11 = fma2(wl1[1], d1, p11);
            p00 = fma2(wl0[2], d2, p00);  p10 = fma2(wl1[2], d2, p10);
            p01 = fma2(wl0[3], d3, p01);  p11 = fma2(wl1[3], d3, p11);
            p00 = fma2(wl0[4], d4, p00);  p10 = fma2(wl1[4], d4, p10);
            p01 = fma2(wl0[5], d5, p01);  p11 = fma2(wl1[5], d5, p11);
            p00 = fma2(wl0[6], d6, p00);  p10 = fma2(wl1[6], d6, p10);
            p01 = fma2(wl0[7], d7, p01);  p11 = fma2(wl1[7], d7, p11);
        }
        // second half (k = 8..15)
        {
            float4 C = tk[2];
            float4 D = tk[3];
            float2 d0 = dup(C.x), d1 = dup(C.y), d2 = dup(C.z), d3 = dup(C.w);
            float2 d4 = dup(D.x), d5 = dup(D.y), d6 = dup(D.z), d7 = dup(D.w);
            p00 = fma2(wl0[8],  d0, p00);  p10 = fma2(wl1[8],  d0, p10);
            p01 = fma2(wl0[9],  d1, p01);  p11 = fma2(wl1[9],  d1, p11);
            p00 = fma2(wl0[10], d2, p00);  p10 = fma2(wl1[10], d2, p10);
            p01 = fma2(wl0[11], d3, p01);  p11 = fma2(wl1[11], d3, p11);
            p00 = fma2(wl0[12], d4, p00);  p10 = fma2(wl1[12], d4, p10);
            p01 = fma2(wl0[13], d5, p01);  p11 = fma2(wl1[13], d5, p11);
            p00 = fma2(wl0[14], d6, p00);  p10 = fma2(wl1[14], d6, p10);
            p01 = fma2(wl0[15], d7, p01);  p11 = fma2(wl1[15], d7, p11);
        }

        float2 acc0 = add2(p00, p01);
        float2 acc1 = add2(p10, p11);

        size_t base = (size_t)(t0 + t) * VOCAB;
        // token*VOCAB is odd-strided -> float2 stores may be 4B-misaligned; scalar STG
        if (a0) logits[base + v0]     = acc0.x;
        if (a1) logits[base + v0 + 1] = acc0.y;
        if (c0) logits[base + v2]     = acc1.x;
        if (c1) logits[base + v2 + 1] = acc1.y;
    }
}

// ---------------------------------------------------------------------------
extern "C" void kernel_launch(void* const* d_in, const int* in_sizes, int n_in,
                              void* d_out, int out_size) {
    const int*   x         = (const int*)  d_in[0];
    const float* emb_table = (const float*)d_in[1];
    const float* Wq        = (const float*)d_in[2];
    const float* bq        = (const float*)d_in[3];
    const float* Wk        = (const float*)d_in[4];
    const float* bk        = (const float*)d_in[5];
    const float* Wv        = (const float*)d_in[6];
    const float* bv        = (const float*)d_in[7];
    const float* Wl        = (const float*)d_in[8];
    const float* bl        = (const float*)d_in[9];
    float* logits          = (float*)d_out;

    qkv_kernel<<<NTOK / 16, 256>>>(x, emb_table, Wq, bq, Wk, bk, Wv, bv);

    dim3 g2(MCW / 8, BS);
    attn_weights_kernel<<<g2, MCW>>>();

    dim3 g3(MCW / 16, BS);
    attn_out_kernel<<<g3, 256>>>();

    dim3 g4((VOCAB + VB - 1) / VB, NTOK / TC);
    logits_kernel<<<g4, 256>>>(Wl, bl, logits);
}